// round 13
// baseline (speedup 1.0000x reference)
#include <cuda_runtime.h>
#include <cuda_bf16.h>
#include <cstdint>

// ---------------- scratch (no allocation allowed) ----------------
__device__ float g_att_h[256 * 1024];
__device__ float g_sc[256 * 200];
__device__ float g_weight[256 * 196];
__device__ float g_part[4 * 256 * 2048];   // K-split partials (shared by both GEMMs)
__device__ __nv_bfloat16 g_WT1h[1024 * 1024];
__device__ __nv_bfloat16 g_WT1l[1024 * 1024];
__device__ __nv_bfloat16 g_WT2h[2048 * 2048];
__device__ __nv_bfloat16 g_WT2l[2048 * 2048];
__device__ __nv_bfloat16 g_hh[256 * 1024];
__device__ __nv_bfloat16 g_hl[256 * 1024];
__device__ __nv_bfloat16 g_arh[256 * 2048];
__device__ __nv_bfloat16 g_arl[256 * 2048];

// ---------------- helpers ----------------
__device__ __forceinline__ uint32_t smem_u32(const void* p) {
    uint32_t a;
    asm("{ .reg .u64 t; cvta.to.shared.u64 t, %1; cvt.u32.u64 %0, t; }" : "=r"(a) : "l"(p));
    return a;
}
__device__ __forceinline__ void ldsm4(uint32_t* r, uint32_t addr) {
    asm volatile("ldmatrix.sync.aligned.m8n8.x4.shared.b16 {%0,%1,%2,%3}, [%4];"
                 : "=r"(r[0]), "=r"(r[1]), "=r"(r[2]), "=r"(r[3]) : "r"(addr));
}
__device__ __forceinline__ void mma16816(float* d, const uint32_t* a, const uint32_t* b) {
    asm volatile(
        "mma.sync.aligned.m16n8k16.row.col.f32.bf16.bf16.f32 "
        "{%0,%1,%2,%3}, {%4,%5,%6,%7}, {%8,%9}, {%0,%1,%2,%3};"
        : "+f"(d[0]), "+f"(d[1]), "+f"(d[2]), "+f"(d[3])
        : "r"(a[0]), "r"(a[1]), "r"(a[2]), "r"(a[3]), "r"(b[0]), "r"(b[1]));
}
__device__ __forceinline__ float fast_tanh(float x) {
    float t; asm("tanh.approx.f32 %0, %1;" : "=f"(t) : "f"(x)); return t;
}
__device__ __forceinline__ float fast_ex2(float x) {
    float t; asm("ex2.approx.f32 %0, %1;" : "=f"(t) : "f"(x)); return t;
}
// gate with 2 MUFU ops: tanh(u) * sigmoid(v), sigmoid(v) = 0.5 + 0.5*tanh(v/2)
__device__ __forceinline__ float gatef(float u, float v) {
    return fast_tanh(u) * (0.5f + 0.5f * fast_tanh(0.5f * v));
}

// ---------------- prep: transpose + bf16 hi/lo split of W [K,N] -> WT [N,K] ----------------
__global__ void __launch_bounds__(256) prep_WT_kernel(
    const float* __restrict__ W, __nv_bfloat16* __restrict__ WTh,
    __nv_bfloat16* __restrict__ WTl, int K, int N)
{
    __shared__ float t[32][33];
    int kx = blockIdx.y * 32, nx = blockIdx.x * 32;
    int tx = threadIdx.x & 31, ty = threadIdx.x >> 5;
#pragma unroll
    for (int i = 0; i < 32; i += 8)
        t[ty + i][tx] = W[(size_t)(kx + ty + i) * N + nx + tx];
    __syncthreads();
#pragma unroll
    for (int i = 0; i < 32; i += 8) {
        float v = t[tx][ty + i];
        __nv_bfloat16 h = __float2bfloat16(v);
        __nv_bfloat16 l = __float2bfloat16(v - __bfloat162float(h));
        size_t o = (size_t)(nx + ty + i) * K + kx + tx;
        WTh[o] = h;
        WTl[o] = l;
    }
}

// ---------------- prep: elementwise bf16 hi/lo split ----------------
__global__ void __launch_bounds__(256) prep_split_kernel(
    const float* __restrict__ x, __nv_bfloat16* __restrict__ xh,
    __nv_bfloat16* __restrict__ xl, int n)
{
    int i = blockIdx.x * 256 + threadIdx.x;
    if (i < n) {
        float v = x[i];
        __nv_bfloat16 h = __float2bfloat16(v);
        xh[i] = h;
        xl[i] = __float2bfloat16(v - __bfloat162float(h));
    }
}

// ---------------- warp-MMA GEMM partial: Cp[z] = A[:, kz] @ B[:, kz]^T ----------------
// 64x64 block tile, BK=32, 128 threads (4 warps, 32x32 each), K-split on blockIdx.z.
#define PAD 40
#define TILE_B (64 * PAD * 2)
__global__ void __launch_bounds__(128) gemm_mma_kernel(
    const __nv_bfloat16* __restrict__ Ah, const __nv_bfloat16* __restrict__ Al,
    const __nv_bfloat16* __restrict__ Bh, const __nv_bfloat16* __restrict__ Bl,
    float* __restrict__ Cpart, int N, int K, int kcnt, int partStride)
{
    __shared__ __nv_bfloat16 smem[2 * 4 * 64 * PAD];
    const uint32_t sbase = smem_u32(smem);

    const int tid = threadIdx.x;
    const int w = tid >> 5;
    const int t = tid & 31;
    const int m0 = (int)blockIdx.y * 64;
    const int n0 = (int)blockIdx.x * 64;
    const int mw = (w & 1) * 32;
    const int nw = (w >> 1) * 32;
    const int koff = (int)blockIdx.z * kcnt * 32;

    const __nv_bfloat16* srcs[4] = {Ah, Al, Bh, Bl};
    uint4 pf[8];
    int prow[8], pq[8];
    const __nv_bfloat16* pg[8];
#pragma unroll
    for (int e = 0; e < 8; e++) {
        int tile = e >> 1;
        int slot = tid + (e & 1) * 128;
        int row = slot >> 2, q = slot & 3;
        prow[e] = row; pq[e] = q;
        int grow = (tile < 2) ? (m0 + row) : (n0 + row);
        pg[e] = srcs[tile] + (size_t)grow * K + koff + q * 8;
    }

    float acc[2][4][4];
#pragma unroll
    for (int i = 0; i < 2; i++)
#pragma unroll
        for (int j = 0; j < 4; j++)
#pragma unroll
            for (int r = 0; r < 4; r++) acc[i][j][r] = 0.0f;

#pragma unroll
    for (int e = 0; e < 8; e++) pf[e] = *(const uint4*)(pg[e]);

    int buf = 0;
    for (int ct = 0; ct < kcnt; ct++) {
        uint32_t bb = sbase + buf * (4 * TILE_B);
#pragma unroll
        for (int e = 0; e < 8; e++) {
            uint32_t addr = bb + (e >> 1) * TILE_B + prow[e] * (PAD * 2) + pq[e] * 16;
            asm volatile("st.shared.v4.b32 [%0], {%1,%2,%3,%4};"
                         :: "r"(addr), "r"(pf[e].x), "r"(pf[e].y), "r"(pf[e].z), "r"(pf[e].w));
        }
        __syncthreads();

        if (ct + 1 < kcnt) {
#pragma unroll
            for (int e = 0; e < 8; e++) pf[e] = *(const uint4*)(pg[e] + (ct + 1) * 32);
        }

        const uint32_t tAh = bb;
        const uint32_t tAl = bb + TILE_B;
        const uint32_t tBh = bb + 2 * TILE_B;
        const uint32_t tBl = bb + 3 * TILE_B;
#pragma unroll
        for (int kk = 0; kk < 2; kk++) {
            uint32_t bhf[2][4], blf[2][4];
#pragma unroll
            for (int jp = 0; jp < 2; jp++) {
                int row = nw + jp * 16 + ((t >> 4) << 3) + (t & 7);
                int col = kk * 16 + (((t >> 3) & 1) << 3);
                uint32_t off = row * (PAD * 2) + col * 2;
                ldsm4(bhf[jp], tBh + off);
                ldsm4(blf[jp], tBl + off);
            }
#pragma unroll
            for (int i = 0; i < 2; i++) {
                int row = mw + i * 16 + (t & 7) + (((t >> 3) & 1) << 3);
                int col = kk * 16 + ((t >> 4) << 3);
                uint32_t off = row * (PAD * 2) + col * 2;
                uint32_t ahf[4], alf[4];
                ldsm4(ahf, tAh + off);
                ldsm4(alf, tAl + off);
#pragma unroll
                for (int j = 0; j < 4; j++) {
                    const uint32_t* bh2 = &bhf[j >> 1][(j & 1) * 2];
                    const uint32_t* bl2 = &blf[j >> 1][(j & 1) * 2];
                    mma16816(acc[i][j], ahf, bh2);
                    mma16816(acc[i][j], ahf, bl2);
                    mma16816(acc[i][j], alf, bh2);
                }
            }
        }
        buf ^= 1;
    }

    float* Cp = Cpart + (size_t)blockIdx.z * partStride;
    const int g = t >> 2;
    const int cbase = n0 + nw + 2 * (t & 3);
#pragma unroll
    for (int i = 0; i < 2; i++) {
#pragma unroll
        for (int j = 0; j < 4; j++) {
            int c = cbase + j * 8;
            int r0 = m0 + mw + i * 16 + g;
            *(float2*)&Cp[(size_t)r0 * N + c] = make_float2(acc[i][j][0], acc[i][j][1]);
            *(float2*)&Cp[(size_t)(r0 + 8) * N + c] = make_float2(acc[i][j][2], acc[i][j][3]);
        }
    }
}

// ---------------- reduce 4 partials + bias -> att_h ----------------
__global__ void __launch_bounds__(256) red4_bias_kernel(
    const float* __restrict__ P, const float* __restrict__ bias,
    float* __restrict__ out)   // 256x1024, partStride 262144 floats (65536 float4)
{
    int idx = blockIdx.x * 256 + threadIdx.x;       // 65536 total
    const float4* p0 = (const float4*)P;
    float4 o = ((const float4*)bias)[idx & 255];
#pragma unroll
    for (int z = 0; z < 4; z++) {
        float4 a = p0[idx + z * 65536];
        o.x += a.x; o.y += a.y; o.z += a.z; o.w += a.w;
    }
    ((float4*)out)[idx] = o;
}

// ---------------- scores (raw) ----------------
__global__ void __launch_bounds__(256) scores_kernel(
    const float* __restrict__ p_att, const float* __restrict__ att_h,
    const float* __restrict__ w_alpha, const float* __restrict__ b_alpha,
    float* __restrict__ sc_out)
{
    __shared__ float ah[1024];
    __shared__ float wa[512];

    const int b = blockIdx.y;
    const int c = blockIdx.x;
    const int tid = threadIdx.x;
    for (int i = tid; i < 1024; i += 256) ah[i] = att_h[b * 1024 + i];
    for (int i = tid; i < 512; i += 256)  wa[i] = w_alpha[i];
    __syncthreads();

    const int lane = tid & 31, warp = tid >> 5;
    const float4* ah1 = (const float4*)ah;
    const float4* ah2 = ah1 + 128;
    const float4* wav = (const float4*)wa;
    const float balpha = b_alpha[0];

    const int sbeg = c * 49;
    for (int sl = warp; sl < 49; sl += 8) {
        int s = sbeg + sl;
        const float4* p = (const float4*)(p_att + ((size_t)b * 196 + s) * 1024);
        float sum = 0.0f;
#pragma unroll
        for (int i = 0; i < 4; i++) {
            int j = lane + (i << 5);
            float4 x = p[j];
            float4 y = p[j + 128];
            float4 a1 = ah1[j];
            float4 a2 = ah2[j];
            float4 w4 = wav[j];
            sum += gatef(x.x + a1.x, y.x + a2.x) * w4.x;
            sum += gatef(x.y + a1.y, y.y + a2.y) * w4.y;
            sum += gatef(x.z + a1.z, y.z + a2.z) * w4.z;
            sum += gatef(x.w + a1.w, y.w + a2.w) * w4.w;
        }
#pragma unroll
        for (int off = 16; off > 0; off >>= 1)
            sum += __shfl_xor_sync(0xffffffffu, sum, off);
        if (lane == 0) sc_out[b * 196 + s] = sum + balpha;
    }
}

// ---------------- softmax over 196 ----------------
__global__ void __launch_bounds__(256) softmax_kernel(
    const float* __restrict__ sc, float* __restrict__ weight)
{
    __shared__ float redm[8], reds[8];
    const int b = blockIdx.x;
    const int tid = threadIdx.x;
    const int lane = tid & 31, warp = tid >> 5;

    float v = (tid < 196) ? sc[b * 196 + tid] : -1e30f;
    float m = v;
#pragma unroll
    for (int off = 16; off > 0; off >>= 1)
        m = fmaxf(m, __shfl_xor_sync(0xffffffffu, m, off));
    if (lane == 0) redm[warp] = m;
    __syncthreads();
    float mall = redm[0];
#pragma unroll
    for (int i = 1; i < 8; i++) mall = fmaxf(mall, redm[i]);

    float e = (tid < 196) ? fast_ex2(1.44269504f * (v - mall)) : 0.0f;
    float ssum = e;
#pragma unroll
    for (int off = 16; off > 0; off >>= 1)
        ssum += __shfl_xor_sync(0xffffffffu, ssum, off);
    if (lane == 0) reds[warp] = ssum;
    __syncthreads();
    float tot = 0.0f;
#pragma unroll
    for (int i = 0; i < 8; i++) tot += reds[i];

    if (tid < 196) weight[b * 196 + tid] = e / tot;
}

// ---------------- att_res = weight @ att_feats, output bf16 hi/lo ----------------
// grid (2, 256), 256 threads: block (hf,b) handles 1024-float half. unroll 14 for MLP.
__global__ void __launch_bounds__(256) att_reduce_kernel(
    const float* __restrict__ att_feats, const float* __restrict__ weight,
    __nv_bfloat16* __restrict__ arh, __nv_bfloat16* __restrict__ arl)
{
    __shared__ float w[196];
    const int b = blockIdx.y;
    const int half = blockIdx.x;
    const int tid = threadIdx.x;
    for (int i = tid; i < 196; i += 256) w[i] = weight[b * 196 + i];
    __syncthreads();

    const float4* basep = (const float4*)(att_feats + (size_t)b * 196 * 2048 + half * 1024) + tid;
    float4 acc = make_float4(0.f, 0.f, 0.f, 0.f);
#pragma unroll 14
    for (int s = 0; s < 196; s++) {
        float4 vv = basep[(size_t)s * 512];
        float ws = w[s];
        acc.x += ws * vv.x; acc.y += ws * vv.y;
        acc.z += ws * vv.z; acc.w += ws * vv.w;
    }
    size_t o = (size_t)b * 2048 + half * 1024 + tid * 4;
    __nv_bfloat162 h0 = __floats2bfloat162_rn(acc.x, acc.y);
    __nv_bfloat162 h1 = __floats2bfloat162_rn(acc.z, acc.w);
    __nv_bfloat162 l0 = __floats2bfloat162_rn(acc.x - __low2float(h0), acc.y - __high2float(h0));
    __nv_bfloat162 l1 = __floats2bfloat162_rn(acc.z - __low2float(h1), acc.w - __high2float(h1));
    *(__nv_bfloat162*)(arh + o) = h0;
    *(__nv_bfloat162*)(arh + o + 2) = h1;
    *(__nv_bfloat162*)(arl + o) = l0;
    *(__nv_bfloat162*)(arl + o + 2) = l1;
}

// ---------------- fused reduce(4 partials)+bias+GLU ----------------
__global__ void __launch_bounds__(256) glu_red4_kernel(
    const float* __restrict__ P, const float* __restrict__ bias,
    float* __restrict__ out)    // partStride 524288 floats
{
    int idx = blockIdx.x * 256 + threadIdx.x;  // 0 .. 262143
    int b = idx >> 10, j = idx & 1023;
    size_t o1 = (size_t)b * 2048 + j;
    size_t o2 = o1 + 1024;
    float x = bias[j];
    float y = bias[1024 + j];
#pragma unroll
    for (int z = 0; z < 4; z++) {
        x += P[o1 + (size_t)z * 524288];
        y += P[o2 + (size_t)z * 524288];
    }
    out[idx] = tanhf(x) * (1.0f / (1.0f + expf(-y)));
}

// ---------------- launch ----------------
extern "C" void kernel_launch(void* const* d_in, const int* in_sizes, int n_in,
                              void* d_out, int out_size)
{
    const float* h         = (const float*)d_in[0];
    const float* att_feats = (const float*)d_in[1];
    const float* p_att     = (const float*)d_in[2];
    const float* W_h2att   = (const float*)d_in[3];
    const float* b_h2att   = (const float*)d_in[4];
    const float* w_alpha   = (const float*)d_in[5];
    const float* b_alpha   = (const float*)d_in[6];
    const float* W_out     = (const float*)d_in[7];
    const float* b_out     = (const float*)d_in[8];
    float* out = (float*)d_out;

    float *att_h_p, *sc_p, *weight_p, *part_p;
    __nv_bfloat16 *WT1h, *WT1l, *WT2h, *WT2l, *hh, *hl, *arh, *arl;
    cudaGetSymbolAddress((void**)&att_h_p, g_att_h);
    cudaGetSymbolAddress((void**)&sc_p, g_sc);
    cudaGetSymbolAddress((void**)&weight_p, g_weight);
    cudaGetSymbolAddress((void**)&part_p, g_part);
    cudaGetSymbolAddress((void**)&WT1h, g_WT1h);
    cudaGetSymbolAddress((void**)&WT1l, g_WT1l);
    cudaGetSymbolAddress((void**)&WT2h, g_WT2h);
    cudaGetSymbolAddress((void**)&WT2l, g_WT2l);
    cudaGetSymbolAddress((void**)&hh, g_hh);
    cudaGetSymbolAddress((void**)&hl, g_hl);
    cudaGetSymbolAddress((void**)&arh, g_arh);
    cudaGetSymbolAddress((void**)&arl, g_arl);

    // one-time stream/event setup (same captured work every call)
    static cudaStream_t s1 = nullptr;
    static cudaEvent_t evFork = nullptr, evPrep2 = nullptr;
    if (s1 == nullptr) {
        cudaStreamCreateWithFlags(&s1, cudaStreamNonBlocking);
        cudaEventCreateWithFlags(&evFork, cudaEventDisableTiming);
        cudaEventCreateWithFlags(&evPrep2, cudaEventDisableTiming);
    }

    // fork: prep_WT2 runs concurrently with the att_h/scores chain
    cudaEventRecord(evFork, 0);
    cudaStreamWaitEvent(s1, evFork, 0);
    prep_WT_kernel<<<dim3(64, 64), 256, 0, s1>>>(W_out, WT2h, WT2l, 2048, 2048);
    cudaEventRecord(evPrep2, s1);

    // main chain (default stream)
    prep_WT_kernel<<<dim3(32, 32), 256>>>(W_h2att, WT1h, WT1l, 1024, 1024);
    prep_split_kernel<<<1024, 256>>>(h, hh, hl, 256 * 1024);

    // 1) att_h partials (K-split 4) + reduce with bias
    gemm_mma_kernel<<<dim3(16, 4, 4), 128>>>(hh, hl, WT1h, WT1l, part_p, 1024, 1024, 8, 262144);
    red4_bias_kernel<<<256, 256>>>(part_p, b_h2att, att_h_p);
    // 2) scores + softmax
    scores_kernel<<<dim3(4, 256), 256>>>(p_att, att_h_p, w_alpha, b_alpha, sc_p);
    softmax_kernel<<<256, 256>>>(sc_p, weight_p);
    // 3) att_res (bf16 hi/lo)
    att_reduce_kernel<<<dim3(2, 256), 256>>>(att_feats, weight_p, arh, arl);

    // join: GEMM2 needs prep_WT2
    cudaStreamWaitEvent(0, evPrep2, 0);
    // 4) lin2 partials (K-split 4) + fused reduce+bias+GLU
    gemm_mma_kernel<<<dim3(32, 4, 4), 128>>>(arh, arl, WT2h, WT2l, part_p, 2048, 2048, 16, 524288);
    glu_red4_kernel<<<1024, 256>>>(part_p, b_out, out);
}

// round 14
// speedup vs baseline: 1.0121x; 1.0121x over previous
#include <cuda_runtime.h>
#include <cuda_bf16.h>
#include <cstdint>

// ---------------- scratch (no allocation allowed) ----------------
__device__ float g_att_h[256 * 1024];
__device__ float g_sc[256 * 200];
__device__ float g_weight[256 * 196];
__device__ float g_part[4 * 256 * 2048];   // K-split partials (shared by both GEMMs)
__device__ __nv_bfloat16 g_WT1h[1024 * 1024];
__device__ __nv_bfloat16 g_WT1l[1024 * 1024];
__device__ __nv_bfloat16 g_WT2h[2048 * 2048];
__device__ __nv_bfloat16 g_WT2l[2048 * 2048];
__device__ __nv_bfloat16 g_hh[256 * 1024];
__device__ __nv_bfloat16 g_hl[256 * 1024];
__device__ __nv_bfloat16 g_arh[256 * 2048];
__device__ __nv_bfloat16 g_arl[256 * 2048];

// ---------------- helpers ----------------
__device__ __forceinline__ uint32_t smem_u32(const void* p) {
    uint32_t a;
    asm("{ .reg .u64 t; cvta.to.shared.u64 t, %1; cvt.u32.u64 %0, t; }" : "=r"(a) : "l"(p));
    return a;
}
__device__ __forceinline__ void ldsm4(uint32_t* r, uint32_t addr) {
    asm volatile("ldmatrix.sync.aligned.m8n8.x4.shared.b16 {%0,%1,%2,%3}, [%4];"
                 : "=r"(r[0]), "=r"(r[1]), "=r"(r[2]), "=r"(r[3]) : "r"(addr));
}
__device__ __forceinline__ void mma16816(float* d, const uint32_t* a, const uint32_t* b) {
    asm volatile(
        "mma.sync.aligned.m16n8k16.row.col.f32.bf16.bf16.f32 "
        "{%0,%1,%2,%3}, {%4,%5,%6,%7}, {%8,%9}, {%0,%1,%2,%3};"
        : "+f"(d[0]), "+f"(d[1]), "+f"(d[2]), "+f"(d[3])
        : "r"(a[0]), "r"(a[1]), "r"(a[2]), "r"(a[3]), "r"(b[0]), "r"(b[1]));
}
#define CP_ASYNC16(dst, src) \
    asm volatile("cp.async.ca.shared.global [%0], [%1], 16;" :: "r"(dst), "l"(src) : "memory")
#define CP_COMMIT() asm volatile("cp.async.commit_group;" ::: "memory")
#define CP_WAIT0()  asm volatile("cp.async.wait_group 0;" ::: "memory")

__device__ __forceinline__ float fast_tanh(float x) {
    float t; asm("tanh.approx.f32 %0, %1;" : "=f"(t) : "f"(x)); return t;
}
__device__ __forceinline__ float fast_ex2(float x) {
    float t; asm("ex2.approx.f32 %0, %1;" : "=f"(t) : "f"(x)); return t;
}
// gate with 2 MUFU ops: tanh(u) * sigmoid(v), sigmoid(v) = 0.5 + 0.5*tanh(v/2)
__device__ __forceinline__ float gatef(float u, float v) {
    return fast_tanh(u) * (0.5f + 0.5f * fast_tanh(0.5f * v));
}

// ---------------- prep: transpose + bf16 hi/lo split of W [K,N] -> WT [N,K] ----------------
__global__ void __launch_bounds__(256) prep_WT_kernel(
    const float* __restrict__ W, __nv_bfloat16* __restrict__ WTh,
    __nv_bfloat16* __restrict__ WTl, int K, int N)
{
    __shared__ float t[32][33];
    int kx = blockIdx.y * 32, nx = blockIdx.x * 32;
    int tx = threadIdx.x & 31, ty = threadIdx.x >> 5;
#pragma unroll
    for (int i = 0; i < 32; i += 8)
        t[ty + i][tx] = W[(size_t)(kx + ty + i) * N + nx + tx];
    __syncthreads();
#pragma unroll
    for (int i = 0; i < 32; i += 8) {
        float v = t[tx][ty + i];
        __nv_bfloat16 h = __float2bfloat16(v);
        __nv_bfloat16 l = __float2bfloat16(v - __bfloat162float(h));
        size_t o = (size_t)(nx + ty + i) * K + kx + tx;
        WTh[o] = h;
        WTl[o] = l;
    }
}

// ---------------- prep: elementwise bf16 hi/lo split ----------------
__global__ void __launch_bounds__(256) prep_split_kernel(
    const float* __restrict__ x, __nv_bfloat16* __restrict__ xh,
    __nv_bfloat16* __restrict__ xl, int n)
{
    int i = blockIdx.x * 256 + threadIdx.x;
    if (i < n) {
        float v = x[i];
        __nv_bfloat16 h = __float2bfloat16(v);
        xh[i] = h;
        xl[i] = __float2bfloat16(v - __bfloat162float(h));
    }
}

// ---------------- warp-MMA GEMM partial: Cp[z] = A[:, kz] @ B[:, kz]^T ----------------
// 64x64 block tile, BK=32, 128 threads (4 warps, 32x32 each), K-split on blockIdx.z.
// cp.async double-buffered staging; SMEM rows padded to 40 bf16 -> conflict-free ldsm.
// hi/lo 3-pass: acc += Ah*Bh + Ah*Bl + Al*Bh.
#define PAD 40
#define TILE_B (64 * PAD * 2)
__global__ void __launch_bounds__(128) gemm_mma_kernel(
    const __nv_bfloat16* __restrict__ Ah, const __nv_bfloat16* __restrict__ Al,
    const __nv_bfloat16* __restrict__ Bh, const __nv_bfloat16* __restrict__ Bl,
    float* __restrict__ Cpart, int N, int K, int kcnt, int partStride)
{
    __shared__ __nv_bfloat16 smem[2 * 4 * 64 * PAD];
    const uint32_t sbase = smem_u32(smem);

    const int tid = threadIdx.x;
    const int w = tid >> 5;
    const int t = tid & 31;
    const int m0 = (int)blockIdx.y * 64;
    const int n0 = (int)blockIdx.x * 64;
    const int mw = (w & 1) * 32;
    const int nw = (w >> 1) * 32;
    const int koff = (int)blockIdx.z * kcnt * 32;

    // staging slots: e -> tile = e>>1 (0:Ah 1:Al 2:Bh 3:Bl), slot = tid + (e&1)*128
    const __nv_bfloat16* srcs[4] = {Ah, Al, Bh, Bl};
    const __nv_bfloat16* pg[8];
    uint32_t sdst[8];
#pragma unroll
    for (int e = 0; e < 8; e++) {
        int tile = e >> 1;
        int slot = tid + (e & 1) * 128;
        int row = slot >> 2, q = slot & 3;
        int grow = (tile < 2) ? (m0 + row) : (n0 + row);
        pg[e] = srcs[tile] + (size_t)grow * K + koff + q * 8;
        sdst[e] = tile * TILE_B + row * (PAD * 2) + q * 16;
    }

    float acc[2][4][4];
#pragma unroll
    for (int i = 0; i < 2; i++)
#pragma unroll
        for (int j = 0; j < 4; j++)
#pragma unroll
            for (int r = 0; r < 4; r++) acc[i][j][r] = 0.0f;

    // prologue: stage chunk 0 into buf 0
#pragma unroll
    for (int e = 0; e < 8; e++) CP_ASYNC16(sbase + sdst[e], pg[e]);
    CP_COMMIT();

    int buf = 0;
    for (int ct = 0; ct < kcnt; ct++) {
        CP_WAIT0();
        __syncthreads();
        // stage next chunk into the other buffer (overlaps with compute below)
        if (ct + 1 < kcnt) {
            uint32_t nb = sbase + (buf ^ 1) * (4 * TILE_B);
#pragma unroll
            for (int e = 0; e < 8; e++) CP_ASYNC16(nb + sdst[e], pg[e] + (ct + 1) * 32);
            CP_COMMIT();
        }

        const uint32_t bb = sbase + buf * (4 * TILE_B);
        const uint32_t tAh = bb;
        const uint32_t tAl = bb + TILE_B;
        const uint32_t tBh = bb + 2 * TILE_B;
        const uint32_t tBl = bb + 3 * TILE_B;
#pragma unroll
        for (int kk = 0; kk < 2; kk++) {
            uint32_t bhf[2][4], blf[2][4];
#pragma unroll
            for (int jp = 0; jp < 2; jp++) {
                int row = nw + jp * 16 + ((t >> 4) << 3) + (t & 7);
                int col = kk * 16 + (((t >> 3) & 1) << 3);
                uint32_t off = row * (PAD * 2) + col * 2;
                ldsm4(bhf[jp], tBh + off);
                ldsm4(blf[jp], tBl + off);
            }
#pragma unroll
            for (int i = 0; i < 2; i++) {
                int row = mw + i * 16 + (t & 7) + (((t >> 3) & 1) << 3);
                int col = kk * 16 + ((t >> 4) << 3);
                uint32_t off = row * (PAD * 2) + col * 2;
                uint32_t ahf[4], alf[4];
                ldsm4(ahf, tAh + off);
                ldsm4(alf, tAl + off);
#pragma unroll
                for (int j = 0; j < 4; j++) {
                    const uint32_t* bh2 = &bhf[j >> 1][(j & 1) * 2];
                    const uint32_t* bl2 = &blf[j >> 1][(j & 1) * 2];
                    mma16816(acc[i][j], ahf, bh2);
                    mma16816(acc[i][j], ahf, bl2);
                    mma16816(acc[i][j], alf, bh2);
                }
            }
        }
        buf ^= 1;
    }

    float* Cp = Cpart + (size_t)blockIdx.z * partStride;
    const int g = t >> 2;
    const int cbase = n0 + nw + 2 * (t & 3);
#pragma unroll
    for (int i = 0; i < 2; i++) {
#pragma unroll
        for (int j = 0; j < 4; j++) {
            int c = cbase + j * 8;
            int r0 = m0 + mw + i * 16 + g;
            *(float2*)&Cp[(size_t)r0 * N + c] = make_float2(acc[i][j][0], acc[i][j][1]);
            *(float2*)&Cp[(size_t)(r0 + 8) * N + c] = make_float2(acc[i][j][2], acc[i][j][3]);
        }
    }
}

// ---------------- reduce 4 partials + bias -> att_h ----------------
__global__ void __launch_bounds__(256) red4_bias_kernel(
    const float* __restrict__ P, const float* __restrict__ bias,
    float* __restrict__ out)   // 256x1024, partStride 262144 floats
{
    int idx = blockIdx.x * 256 + threadIdx.x;       // 65536 total float4
    const float4* p0 = (const float4*)P;
    float4 o = ((const float4*)bias)[idx & 255];
#pragma unroll
    for (int z = 0; z < 4; z++) {
        float4 a = p0[idx + z * 65536];
        o.x += a.x; o.y += a.y; o.z += a.z; o.w += a.w;
    }
    ((float4*)out)[idx] = o;
}

// ---------------- scores (raw) ----------------
__global__ void __launch_bounds__(256) scores_kernel(
    const float* __restrict__ p_att, const float* __restrict__ att_h,
    const float* __restrict__ w_alpha, const float* __restrict__ b_alpha,
    float* __restrict__ sc_out)
{
    __shared__ float ah[1024];
    __shared__ float wa[512];

    const int b = blockIdx.y;
    const int c = blockIdx.x;
    const int tid = threadIdx.x;
    for (int i = tid; i < 1024; i += 256) ah[i] = att_h[b * 1024 + i];
    for (int i = tid; i < 512; i += 256)  wa[i] = w_alpha[i];
    __syncthreads();

    const int lane = tid & 31, warp = tid >> 5;
    const float4* ah1 = (const float4*)ah;
    const float4* ah2 = ah1 + 128;
    const float4* wav = (const float4*)wa;
    const float balpha = b_alpha[0];

    const int sbeg = c * 49;
    for (int sl = warp; sl < 49; sl += 8) {
        int s = sbeg + sl;
        const float4* p = (const float4*)(p_att + ((size_t)b * 196 + s) * 1024);
        float sum = 0.0f;
#pragma unroll
        for (int i = 0; i < 4; i++) {
            int j = lane + (i << 5);
            float4 x = p[j];
            float4 y = p[j + 128];
            float4 a1 = ah1[j];
            float4 a2 = ah2[j];
            float4 w4 = wav[j];
            sum += gatef(x.x + a1.x, y.x + a2.x) * w4.x;
            sum += gatef(x.y + a1.y, y.y + a2.y) * w4.y;
            sum += gatef(x.z + a1.z, y.z + a2.z) * w4.z;
            sum += gatef(x.w + a1.w, y.w + a2.w) * w4.w;
        }
#pragma unroll
        for (int off = 16; off > 0; off >>= 1)
            sum += __shfl_xor_sync(0xffffffffu, sum, off);
        if (lane == 0) sc_out[b * 196 + s] = sum + balpha;
    }
}

// ---------------- softmax over 196 ----------------
__global__ void __launch_bounds__(256) softmax_kernel(
    const float* __restrict__ sc, float* __restrict__ weight)
{
    __shared__ float redm[8], reds[8];
    const int b = blockIdx.x;
    const int tid = threadIdx.x;
    const int lane = tid & 31, warp = tid >> 5;

    float v = (tid < 196) ? sc[b * 196 + tid] : -1e30f;
    float m = v;
#pragma unroll
    for (int off = 16; off > 0; off >>= 1)
        m = fmaxf(m, __shfl_xor_sync(0xffffffffu, m, off));
    if (lane == 0) redm[warp] = m;
    __syncthreads();
    float mall = redm[0];
#pragma unroll
    for (int i = 1; i < 8; i++) mall = fmaxf(mall, redm[i]);

    float e = (tid < 196) ? fast_ex2(1.44269504f * (v - mall)) : 0.0f;
    float ssum = e;
#pragma unroll
    for (int off = 16; off > 0; off >>= 1)
        ssum += __shfl_xor_sync(0xffffffffu, ssum, off);
    if (lane == 0) reds[warp] = ssum;
    __syncthreads();
    float tot = 0.0f;
#pragma unroll
    for (int i = 0; i < 8; i++) tot += reds[i];

    if (tid < 196) weight[b * 196 + tid] = e / tot;
}

// ---------------- att_res = weight @ att_feats, output bf16 hi/lo ----------------
// grid (4, 256), 128 threads: block (q,b) handles 512-float quarter q.
__global__ void __launch_bounds__(128) att_reduce_kernel(
    const float* __restrict__ att_feats, const float* __restrict__ weight,
    __nv_bfloat16* __restrict__ arh, __nv_bfloat16* __restrict__ arl)
{
    __shared__ float w[196];
    const int b = blockIdx.y;
    const int qtr = blockIdx.x;
    const int tid = threadIdx.x;
    for (int i = tid; i < 196; i += 128) w[i] = weight[b * 196 + i];
    __syncthreads();

    const float4* basep = (const float4*)(att_feats + (size_t)b * 196 * 2048 + qtr * 512) + tid;
    float4 acc = make_float4(0.f, 0.f, 0.f, 0.f);
#pragma unroll 7
    for (int s = 0; s < 196; s++) {
        float4 vv = basep[(size_t)s * 512];
        float ws = w[s];
        acc.x += ws * vv.x; acc.y += ws * vv.y;
        acc.z += ws * vv.z; acc.w += ws * vv.w;
    }
    size_t o = (size_t)b * 2048 + qtr * 512 + tid * 4;
    __nv_bfloat162 h0 = __floats2bfloat162_rn(acc.x, acc.y);
    __nv_bfloat162 h1 = __floats2bfloat162_rn(acc.z, acc.w);
    __nv_bfloat162 l0 = __floats2bfloat162_rn(acc.x - __low2float(h0), acc.y - __high2float(h0));
    __nv_bfloat162 l1 = __floats2bfloat162_rn(acc.z - __low2float(h1), acc.w - __high2float(h1));
    *(__nv_bfloat162*)(arh + o) = h0;
    *(__nv_bfloat162*)(arh + o + 2) = h1;
    *(__nv_bfloat162*)(arl + o) = l0;
    *(__nv_bfloat162*)(arl + o + 2) = l1;
}

// ---------------- fused reduce(4 partials)+bias+GLU ----------------
__global__ void __launch_bounds__(256) glu_red4_kernel(
    const float* __restrict__ P, const float* __restrict__ bias,
    float* __restrict__ out)    // partStride 524288 floats
{
    int idx = blockIdx.x * 256 + threadIdx.x;  // 0 .. 262143
    int b = idx >> 10, j = idx & 1023;
    size_t o1 = (size_t)b * 2048 + j;
    size_t o2 = o1 + 1024;
    float x = bias[j];
    float y = bias[1024 + j];
#pragma unroll
    for (int z = 0; z < 4; z++) {
        x += P[o1 + (size_t)z * 524288];
        y += P[o2 + (size_t)z * 524288];
    }
    out[idx] = tanhf(x) * (1.0f / (1.0f + expf(-y)));
}

// ---------------- launch ----------------
extern "C" void kernel_launch(void* const* d_in, const int* in_sizes, int n_in,
                              void* d_out, int out_size)
{
    const float* h         = (const float*)d_in[0];
    const float* att_feats = (const float*)d_in[1];
    const float* p_att     = (const float*)d_in[2];
    const float* W_h2att   = (const float*)d_in[3];
    const float* b_h2att   = (const float*)d_in[4];
    const float* w_alpha   = (const float*)d_in[5];
    const float* b_alpha   = (const float*)d_in[6];
    const float* W_out     = (const float*)d_in[7];
    const float* b_out     = (const float*)d_in[8];
    float* out = (float*)d_out;

    float *att_h_p, *sc_p, *weight_p, *part_p;
    __nv_bfloat16 *WT1h, *WT1l, *WT2h, *WT2l, *hh, *hl, *arh, *arl;
    cudaGetSymbolAddress((void**)&att_h_p, g_att_h);
    cudaGetSymbolAddress((void**)&sc_p, g_sc);
    cudaGetSymbolAddress((void**)&weight_p, g_weight);
    cudaGetSymbolAddress((void**)&part_p, g_part);
    cudaGetSymbolAddress((void**)&WT1h, g_WT1h);
    cudaGetSymbolAddress((void**)&WT1l, g_WT1l);
    cudaGetSymbolAddress((void**)&WT2h, g_WT2h);
    cudaGetSymbolAddress((void**)&WT2l, g_WT2l);
    cudaGetSymbolAddress((void**)&hh, g_hh);
    cudaGetSymbolAddress((void**)&hl, g_hl);
    cudaGetSymbolAddress((void**)&arh, g_arh);
    cudaGetSymbolAddress((void**)&arl, g_arl);

    // prep (single stream — stream fork measured as a regression in R10/R13)
    prep_WT_kernel<<<dim3(32, 32), 256>>>(W_h2att, WT1h, WT1l, 1024, 1024);
    prep_WT_kernel<<<dim3(64, 64), 256>>>(W_out, WT2h, WT2l, 2048, 2048);
    prep_split_kernel<<<1024, 256>>>(h, hh, hl, 256 * 1024);

    // 1) att_h partials (K-split 4) + reduce with bias
    gemm_mma_kernel<<<dim3(16, 4, 4), 128>>>(hh, hl, WT1h, WT1l, part_p, 1024, 1024, 8, 262144);
    red4_bias_kernel<<<256, 256>>>(part_p, b_h2att, att_h_p);
    // 2) scores + softmax
    scores_kernel<<<dim3(4, 256), 256>>>(p_att, att_h_p, w_alpha, b_alpha, sc_p);
    softmax_kernel<<<256, 256>>>(sc_p, weight_p);
    // 3) att_res (bf16 hi/lo)
    att_reduce_kernel<<<dim3(4, 256), 128>>>(att_feats, weight_p, arh, arl);
    // 4) lin2 partials (K-split 4) + fused reduce+bias+GLU
    gemm_mma_kernel<<<dim3(32, 4, 4), 128>>>(arh, arl, WT2h, WT2l, part_p, 2048, 2048, 16, 524288);
    glu_red4_kernel<<<1024, 256>>>(part_p, b_out, out);
}

// round 17
// speedup vs baseline: 1.0457x; 1.0332x over previous
#include <cuda_runtime.h>
#include <cuda_bf16.h>
#include <cstdint>

// ---------------- scratch (no allocation allowed) ----------------
__device__ float g_att_h[256 * 1024];
__device__ float g_sc[256 * 200];
__device__ float g_weight[256 * 196];
__device__ float g_part[4 * 256 * 2048];   // K-split partials (shared by both GEMMs)
__device__ __nv_bfloat16 g_arh[256 * 2048];
__device__ __nv_bfloat16 g_arl[256 * 2048];

// ---------------- helpers ----------------
__device__ __forceinline__ uint32_t smem_u32(const void* p) {
    uint32_t a;
    asm("{ .reg .u64 t; cvta.to.shared.u64 t, %1; cvt.u32.u64 %0, t; }" : "=r"(a) : "l"(p));
    return a;
}
__device__ __forceinline__ void ldsm4(uint32_t* r, uint32_t addr) {
    asm volatile("ldmatrix.sync.aligned.m8n8.x4.shared.b16 {%0,%1,%2,%3}, [%4];"
                 : "=r"(r[0]), "=r"(r[1]), "=r"(r[2]), "=r"(r[3]) : "r"(addr));
}
__device__ __forceinline__ void mma16816(float* d, const uint32_t* a, const uint32_t* b) {
    asm volatile(
        "mma.sync.aligned.m16n8k16.row.col.f32.bf16.bf16.f32 "
        "{%0,%1,%2,%3}, {%4,%5,%6,%7}, {%8,%9}, {%0,%1,%2,%3};"
        : "+f"(d[0]), "+f"(d[1]), "+f"(d[2]), "+f"(d[3])
        : "r"(a[0]), "r"(a[1]), "r"(a[2]), "r"(a[3]), "r"(b[0]), "r"(b[1]));
}
#define CP_ASYNC16(dst, src) \
    asm volatile("cp.async.ca.shared.global [%0], [%1], 16;" :: "r"(dst), "l"(src) : "memory")
#define CP_COMMIT() asm volatile("cp.async.commit_group;" ::: "memory")
#define CP_WAIT0()  asm volatile("cp.async.wait_group 0;" ::: "memory")

__device__ __forceinline__ float fast_tanh(float x) {
    float t; asm("tanh.approx.f32 %0, %1;" : "=f"(t) : "f"(x)); return t;
}
__device__ __forceinline__ float fast_ex2(float x) {
    float t; asm("ex2.approx.f32 %0, %1;" : "=f"(t) : "f"(x)); return t;
}
__device__ __forceinline__ float fast_rcp(float x) {
    float t; asm("rcp.approx.f32 %0, %1;" : "=f"(t) : "f"(x)); return t;
}
__device__ __forceinline__ float gatef(float u, float v) {
    float e = fast_ex2(-1.44269504f * v);
    return fast_tanh(u) * fast_rcp(1.0f + e);
}

// ---------------- fused-conversion warp-MMA GEMM ----------------
// Cpart[z] = A[:, kz] @ W[kz, :]  (partial, no bias)
// A: AFP32 ? fp32 [M,K] row-major (converted to bf16 hi/lo in registers)
//          : bf16 hi/lo pair [M,K] row-major
// W: fp32 [K,N] row-major -> transposed + hi/lo split in SMEM (no prep kernel)
// Block tile 64x64, BK=32, 128 threads (4 warps, 32x32), K-split on blockIdx.z.
// hi/lo 3-pass: acc += Ah*Bh + Ah*Bl + Al*Bh.
#define PAD 40
#define TILE_B 5120                 // 64 rows * 40 bf16 * 2B
#define BUF_BF16 (4 * TILE_B)       // Ah, Al, Bh, Bl
#define FP32_OFF (2 * BUF_BF16)     // 40960
#define FP32_BUF 8704               // 32 rows * 68 floats * 4B
#define SMEM_TOTAL_GEMM (FP32_OFF + 2 * FP32_BUF)   // 58368

template <bool AFP32>
__global__ void __launch_bounds__(128) gemm_conv_kernel(
    const float* __restrict__ Af,
    const __nv_bfloat16* __restrict__ Abh, const __nv_bfloat16* __restrict__ Abl,
    const float* __restrict__ W,
    float* __restrict__ Cpart, int N, int K, int kcnt, int partStride)
{
    extern __shared__ char smem[];
    const uint32_t sbase = smem_u32(smem);

    const int tid = threadIdx.x;
    const int w = tid >> 5;
    const int t = tid & 31;
    const int m0 = (int)blockIdx.y * 64;
    const int n0 = (int)blockIdx.x * 64;
    const int mw = (w & 1) * 32;
    const int nw = (w >> 1) * 32;
    const int koff = (int)blockIdx.z * kcnt * 32;

    // ---- B fp32 staging slots: 4 cp.async per thread per chunk ----
    int brow[4], bc4[4];
#pragma unroll
    for (int s = 0; s < 4; s++) {
        int slot = tid + s * 128;            // 0..511
        brow[s] = slot >> 4;                 // 0..31 (k row)
        bc4[s] = slot & 15;                  // 16B col group
    }

    // ---- A staging for bf16 mode (4 uint4 slots) ----
    const __nv_bfloat16* pgA[4];
    uint32_t adst[4];
    if (!AFP32) {
#pragma unroll
        for (int e = 0; e < 4; e++) {
            int slot = tid + (e & 1) * 128;  // 0..255
            int row = slot >> 2, q = slot & 3;
            int tile = e >> 1;               // 0:Ah 1:Al
            pgA[e] = (tile ? Abl : Abh) + (size_t)(m0 + row) * K + koff + q * 8;
            adst[e] = tile * TILE_B + row * (PAD * 2) + q * 16;
        }
    }
    // ---- A fp32 mode: per-thread row/half ----
    const int am = tid >> 1;                 // 0..63
    const int akh = tid & 1;                 // 16-k half

    float acc[2][4][4];
#pragma unroll
    for (int i = 0; i < 2; i++)
#pragma unroll
        for (int j = 0; j < 4; j++)
#pragma unroll
            for (int r = 0; r < 4; r++) acc[i][j][r] = 0.0f;

    // prologue: stage B fp32 chunk 0 -> fp32 buf 0
#pragma unroll
    for (int s = 0; s < 4; s++) {
        const float* src = W + (size_t)(koff + brow[s]) * N + n0 + bc4[s] * 4;
        CP_ASYNC16(sbase + FP32_OFF + brow[s] * 272 + bc4[s] * 16, src);
    }
    CP_COMMIT();

    // prologue: A chunk 0 into regs
    float4 afr[4];
    uint4 afu[4];
    if (AFP32) {
        const float4* src = (const float4*)(Af + (size_t)(m0 + am) * K + koff + akh * 16);
#pragma unroll
        for (int i = 0; i < 4; i++) afr[i] = src[i];
    } else {
#pragma unroll
        for (int e = 0; e < 4; e++) afu[e] = *(const uint4*)(pgA[e]);
    }

    int buf = 0;
    for (int ct = 0; ct < kcnt; ct++) {
        CP_WAIT0();
        __syncthreads();   // B fp32(ct) visible; all compute on this buf done

        const uint32_t bb = sbase + buf * BUF_BF16;

        // ---- stage A (convert if fp32) ----
        if (AFP32) {
            uint32_t hi[8], lo[8];
#pragma unroll
            for (int i = 0; i < 8; i++) {
                float v0 = ((const float*)afr)[2 * i];
                float v1 = ((const float*)afr)[2 * i + 1];
                __nv_bfloat162 h2 = __floats2bfloat162_rn(v0, v1);
                hi[i] = *(uint32_t*)&h2;
                __nv_bfloat162 l2 = __floats2bfloat162_rn(
                    v0 - __bfloat162float(__low2bfloat16(h2)),
                    v1 - __bfloat162float(__high2bfloat16(h2)));
                lo[i] = *(uint32_t*)&l2;
            }
            uint32_t da = bb + am * (PAD * 2) + akh * 32;
            asm volatile("st.shared.v4.b32 [%0], {%1,%2,%3,%4};"
                         :: "r"(da), "r"(hi[0]), "r"(hi[1]), "r"(hi[2]), "r"(hi[3]));
            asm volatile("st.shared.v4.b32 [%0], {%1,%2,%3,%4};"
                         :: "r"(da + 16), "r"(hi[4]), "r"(hi[5]), "r"(hi[6]), "r"(hi[7]));
            asm volatile("st.shared.v4.b32 [%0], {%1,%2,%3,%4};"
                         :: "r"(da + TILE_B), "r"(lo[0]), "r"(lo[1]), "r"(lo[2]), "r"(lo[3]));
            asm volatile("st.shared.v4.b32 [%0], {%1,%2,%3,%4};"
                         :: "r"(da + TILE_B + 16), "r"(lo[4]), "r"(lo[5]), "r"(lo[6]), "r"(lo[7]));
        } else {
#pragma unroll
            for (int e = 0; e < 4; e++) {
                asm volatile("st.shared.v4.b32 [%0], {%1,%2,%3,%4};"
                             :: "r"(bb + adst[e]),
                                "r"(afu[e].x), "r"(afu[e].y), "r"(afu[e].z), "r"(afu[e].w));
            }
        }

        // ---- convert B fp32 -> bf16 hi/lo (transpose) ----
        {
            const float* st = (const float*)(smem + FP32_OFF) + buf * (FP32_BUF / 4);
            int n = tid >> 1, kh = tid & 1;
            uint32_t hi[8], lo[8];
#pragma unroll
            for (int i = 0; i < 8; i++) {
                float v0 = st[(kh * 16 + 2 * i) * 68 + n];
                float v1 = st[(kh * 16 + 2 * i + 1) * 68 + n];
                __nv_bfloat162 h2 = __floats2bfloat162_rn(v0, v1);
                hi[i] = *(uint32_t*)&h2;
                __nv_bfloat162 l2 = __floats2bfloat162_rn(
                    v0 - __bfloat162float(__low2bfloat16(h2)),
                    v1 - __bfloat162float(__high2bfloat16(h2)));
                lo[i] = *(uint32_t*)&l2;
            }
            uint32_t db = bb + 2 * TILE_B + n * (PAD * 2) + kh * 32;
            asm volatile("st.shared.v4.b32 [%0], {%1,%2,%3,%4};"
                         :: "r"(db), "r"(hi[0]), "r"(hi[1]), "r"(hi[2]), "r"(hi[3]));
            asm volatile("st.shared.v4.b32 [%0], {%1,%2,%3,%4};"
                         :: "r"(db + 16), "r"(hi[4]), "r"(hi[5]), "r"(hi[6]), "r"(hi[7]));
            asm volatile("st.shared.v4.b32 [%0], {%1,%2,%3,%4};"
                         :: "r"(db + TILE_B), "r"(lo[0]), "r"(lo[1]), "r"(lo[2]), "r"(lo[3]));
            asm volatile("st.shared.v4.b32 [%0], {%1,%2,%3,%4};"
                         :: "r"(db + TILE_B + 16), "r"(lo[4]), "r"(lo[5]), "r"(lo[6]), "r"(lo[7]));
        }

        // ---- issue next chunk loads (overlap with compute) ----
        if (ct + 1 < kcnt) {
            int kofn = koff + (ct + 1) * 32;
            uint32_t nf = sbase + FP32_OFF + (buf ^ 1) * FP32_BUF;
#pragma unroll
            for (int s = 0; s < 4; s++) {
                const float* src = W + (size_t)(kofn + brow[s]) * N + n0 + bc4[s] * 4;
                CP_ASYNC16(nf + brow[s] * 272 + bc4[s] * 16, src);
            }
            CP_COMMIT();
            if (AFP32) {
                const float4* src = (const float4*)(Af + (size_t)(m0 + am) * K + kofn + akh * 16);
#pragma unroll
                for (int i = 0; i < 4; i++) afr[i] = src[i];
            } else {
#pragma unroll
                for (int e = 0; e < 4; e++) afu[e] = *(const uint4*)(pgA[e] + (ct + 1) * 32);
            }
        }
        __syncthreads();   // bf16 tiles ready

        // ---- compute ----
        const uint32_t tAh = bb;
        const uint32_t tAl = bb + TILE_B;
        const uint32_t tBh = bb + 2 * TILE_B;
        const uint32_t tBl = bb + 3 * TILE_B;
#pragma unroll
        for (int kk = 0; kk < 2; kk++) {
            uint32_t bhf[2][4], blf[2][4];
#pragma unroll
            for (int jp = 0; jp < 2; jp++) {
                int row = nw + jp * 16 + ((t >> 4) << 3) + (t & 7);
                int col = kk * 16 + (((t >> 3) & 1) << 3);
                uint32_t off = row * (PAD * 2) + col * 2;
                ldsm4(bhf[jp], tBh + off);
                ldsm4(blf[jp], tBl + off);
            }
#pragma unroll
            for (int i = 0; i < 2; i++) {
                int row = mw + i * 16 + (t & 7) + (((t >> 3) & 1) << 3);
                int col = kk * 16 + ((t >> 4) << 3);
                uint32_t off = row * (PAD * 2) + col * 2;
                uint32_t ahf[4], alf[4];
                ldsm4(ahf, tAh + off);
                ldsm4(alf, tAl + off);
#pragma unroll
                for (int j = 0; j < 4; j++) {
                    const uint32_t* bh2 = &bhf[j >> 1][(j & 1) * 2];
                    const uint32_t* bl2 = &blf[j >> 1][(j & 1) * 2];
                    mma16816(acc[i][j], ahf, bh2);
                    mma16816(acc[i][j], ahf, bl2);
                    mma16816(acc[i][j], alf, bh2);
                }
            }
        }
        buf ^= 1;
    }

    float* Cp = Cpart + (size_t)blockIdx.z * partStride;
    const int g = t >> 2;
    const int cbase = n0 + nw + 2 * (t & 3);
#pragma unroll
    for (int i = 0; i < 2; i++) {
#pragma unroll
        for (int j = 0; j < 4; j++) {
            int c = cbase + j * 8;
            int r0 = m0 + mw + i * 16 + g;
            *(float2*)&Cp[(size_t)r0 * N + c] = make_float2(acc[i][j][0], acc[i][j][1]);
            *(float2*)&Cp[(size_t)(r0 + 8) * N + c] = make_float2(acc[i][j][2], acc[i][j][3]);
        }
    }
}

// ---------------- reduce 4 partials + bias -> att_h ----------------
__global__ void __launch_bounds__(256) red4_bias_kernel(
    const float* __restrict__ P, const float* __restrict__ bias,
    float* __restrict__ out)   // 256x1024, partStride 262144 floats
{
    int idx = blockIdx.x * 256 + threadIdx.x;       // 65536 total float4
    const float4* p0 = (const float4*)P;
    float4 o = ((const float4*)bias)[idx & 255];
#pragma unroll
    for (int z = 0; z < 4; z++) {
        float4 a = p0[idx + z * 65536];
        o.x += a.x; o.y += a.y; o.z += a.z; o.w += a.w;
    }
    ((float4*)out)[idx] = o;
}

// ---------------- scores (raw) ----------------
__global__ void __launch_bounds__(256) scores_kernel(
    const float* __restrict__ p_att, const float* __restrict__ att_h,
    const float* __restrict__ w_alpha, const float* __restrict__ b_alpha,
    float* __restrict__ sc_out)
{
    __shared__ float ah[1024];
    __shared__ float wa[512];

    const int b = blockIdx.y;
    const int c = blockIdx.x;
    const int tid = threadIdx.x;
    for (int i = tid; i < 1024; i += 256) ah[i] = att_h[b * 1024 + i];
    for (int i = tid; i < 512; i += 256)  wa[i] = w_alpha[i];
    __syncthreads();

    const int lane = tid & 31, warp = tid >> 5;
    const float4* ah1 = (const float4*)ah;
    const float4* ah2 = ah1 + 128;
    const float4* wav = (const float4*)wa;
    const float balpha = b_alpha[0];

    const int sbeg = c * 49;
    for (int sl = warp; sl < 49; sl += 8) {
        int s = sbeg + sl;
        const float4* p = (const float4*)(p_att + ((size_t)b * 196 + s) * 1024);
        float sum = 0.0f;
#pragma unroll
        for (int i = 0; i < 4; i++) {
            int j = lane + (i << 5);
            float4 x = p[j];
            float4 y = p[j + 128];
            float4 a1 = ah1[j];
            float4 a2 = ah2[j];
            float4 w4 = wav[j];
            sum += gatef(x.x + a1.x, y.x + a2.x) * w4.x;
            sum += gatef(x.y + a1.y, y.y + a2.y) * w4.y;
            sum += gatef(x.z + a1.z, y.z + a2.z) * w4.z;
            sum += gatef(x.w + a1.w, y.w + a2.w) * w4.w;
        }
#pragma unroll
        for (int off = 16; off > 0; off >>= 1)
            sum += __shfl_xor_sync(0xffffffffu, sum, off);
        if (lane == 0) sc_out[b * 196 + s] = sum + balpha;
    }
}

// ---------------- softmax over 196 ----------------
__global__ void __launch_bounds__(256) softmax_kernel(
    const float* __restrict__ sc, float* __restrict__ weight)
{
    __shared__ float redm[8], reds[8];
    const int b = blockIdx.x;
    const int tid = threadIdx.x;
    const int lane = tid & 31, warp = tid >> 5;

    float v = (tid < 196) ? sc[b * 196 + tid] : -1e30f;
    float m = v;
#pragma unroll
    for (int off = 16; off > 0; off >>= 1)
        m = fmaxf(m, __shfl_xor_sync(0xffffffffu, m, off));
    if (lane == 0) redm[warp] = m;
    __syncthreads();
    float mall = redm[0];
#pragma unroll
    for (int i = 1; i < 8; i++) mall = fmaxf(mall, redm[i]);

    float e = (tid < 196) ? fast_ex2(1.44269504f * (v - mall)) : 0.0f;
    float ssum = e;
#pragma unroll
    for (int off = 16; off > 0; off >>= 1)
        ssum += __shfl_xor_sync(0xffffffffu, ssum, off);
    if (lane == 0) reds[warp] = ssum;
    __syncthreads();
    float tot = 0.0f;
#pragma unroll
    for (int i = 0; i < 8; i++) tot += reds[i];

    if (tid < 196) weight[b * 196 + tid] = e / tot;
}

// ---------------- att_res = weight @ att_feats, output bf16 hi/lo ----------------
__global__ void __launch_bounds__(128) att_reduce_kernel(
    const float* __restrict__ att_feats, const float* __restrict__ weight,
    __nv_bfloat16* __restrict__ arh, __nv_bfloat16* __restrict__ arl)
{
    __shared__ float w[196];
    const int b = blockIdx.y;
    const int qtr = blockIdx.x;
    const int tid = threadIdx.x;
    for (int i = tid; i < 196; i += 128) w[i] = weight[b * 196 + i];
    __syncthreads();

    const float4* basep = (const float4*)(att_feats + (size_t)b * 196 * 2048 + qtr * 512) + tid;
    float4 acc = make_float4(0.f, 0.f, 0.f, 0.f);
#pragma unroll 7
    for (int s = 0; s < 196; s++) {
        float4 vv = basep[(size_t)s * 512];
        float ws = w[s];
        acc.x += ws * vv.x; acc.y += ws * vv.y;
        acc.z += ws * vv.z; acc.w += ws * vv.w;
    }
    size_t o = (size_t)b * 2048 + qtr * 512 + tid * 4;
    __nv_bfloat162 h0 = __floats2bfloat162_rn(acc.x, acc.y);
    __nv_bfloat162 h1 = __floats2bfloat162_rn(acc.z, acc.w);
    __nv_bfloat162 l0 = __floats2bfloat162_rn(acc.x - __low2float(h0), acc.y - __high2float(h0));
    __nv_bfloat162 l1 = __floats2bfloat162_rn(acc.z - __low2float(h1), acc.w - __high2float(h1));
    *(__nv_bfloat162*)(arh + o) = h0;
    *(__nv_bfloat162*)(arh + o + 2) = h1;
    *(__nv_bfloat162*)(arl + o) = l0;
    *(__nv_bfloat162*)(arl + o + 2) = l1;
}

// ---------------- fused reduce(4 partials)+bias+GLU ----------------
__global__ void __launch_bounds__(256) glu_red4_kernel(
    const float* __restrict__ P, const float* __restrict__ bias,
    float* __restrict__ out)    // partStride 524288 floats
{
    int idx = blockIdx.x * 256 + threadIdx.x;  // 0 .. 262143
    int b = idx >> 10, j = idx & 1023;
    size_t o1 = (size_t)b * 2048 + j;
    size_t o2 = o1 + 1024;
    float x = bias[j];
    float y = bias[1024 + j];
#pragma unroll
    for (int z = 0; z < 4; z++) {
        x += P[o1 + (size_t)z * 524288];
        y += P[o2 + (size_t)z * 524288];
    }
    out[idx] = tanhf(x) * (1.0f / (1.0f + expf(-y)));
}

// ---------------- launch ----------------
extern "C" void kernel_launch(void* const* d_in, const int* in_sizes, int n_in,
                              void* d_out, int out_size)
{
    const float* h         = (const float*)d_in[0];
    const float* att_feats = (const float*)d_in[1];
    const float* p_att     = (const float*)d_in[2];
    const float* W_h2att   = (const float*)d_in[3];
    const float* b_h2att   = (const float*)d_in[4];
    const float* w_alpha   = (const float*)d_in[5];
    const float* b_alpha   = (const float*)d_in[6];
    const float* W_out     = (const float*)d_in[7];
    const float* b_out     = (const float*)d_in[8];
    float* out = (float*)d_out;

    float *att_h_p, *sc_p, *weight_p, *part_p;
    __nv_bfloat16 *arh, *arl;
    cudaGetSymbolAddress((void**)&att_h_p, g_att_h);
    cudaGetSymbolAddress((void**)&sc_p, g_sc);
    cudaGetSymbolAddress((void**)&weight_p, g_weight);
    cudaGetSymbolAddress((void**)&part_p, g_part);
    cudaGetSymbolAddress((void**)&arh, g_arh);
    cudaGetSymbolAddress((void**)&arl, g_arl);

    // unconditional, idempotent, capture-legal (no statics in this function)
    cudaFuncSetAttribute(gemm_conv_kernel<true>,
                         cudaFuncAttributeMaxDynamicSharedMemorySize, SMEM_TOTAL_GEMM);
    cudaFuncSetAttribute(gemm_conv_kernel<false>,
                         cudaFuncAttributeMaxDynamicSharedMemorySize, SMEM_TOTAL_GEMM);

    // 1) att_h partials (K-split 4, fused fp32->bf16 conversion) + reduce with bias
    gemm_conv_kernel<true><<<dim3(16, 4, 4), 128, SMEM_TOTAL_GEMM>>>(
        h, nullptr, nullptr, W_h2att, part_p, 1024, 1024, 8, 262144);
    red4_bias_kernel<<<256, 256>>>(part_p, b_h2att, att_h_p);
    // 2) scores + softmax
    scores_kernel<<<dim3(4, 256), 256>>>(p_att, att_h_p, w_alpha, b_alpha, sc_p);
    softmax_kernel<<<256, 256>>>(sc_p, weight_p);
    // 3) att_res (bf16 hi/lo)
    att_reduce_kernel<<<dim3(4, 256), 128>>>(att_feats, weight_p, arh, arl);
    // 4) lin2 partials (K-split 4, fused W conversion) + fused reduce+bias+GLU
    gemm_conv_kernel<false><<<dim3(32, 4, 4), 128, SMEM_TOTAL_GEMM>>>(
        nullptr, arh, arl, W_out, part_p, 2048, 2048, 16, 524288);
    glu_red4_kernel<<<1024, 256>>>(part_p, b_out, out);
}